// round 2
// baseline (speedup 1.0000x reference)
#include <cuda_runtime.h>
#include <math.h>

#define BB   128
#define NNOD 50
#define SEQ  51
#define DIM  128
#define NH   8
#define DHE  16
#define FFD  512
#define NLE  6
#define NLD  2
#define MTOT (BB*SEQ)            // 6528
#define SZ_MD (MTOT*DIM)         // 835584

// ---------------- scratch (single device array, no allocations) ----------------
// layout (floats):
//  h:      [0,            SZ_MD)
//  t:      [SZ_MD,        2*SZ_MD)
//  Q:      [2*SZ_MD, 3*SZ_MD)
//  K:      [3*SZ_MD, 4*SZ_MD)
//  V:      [4*SZ_MD, 5*SZ_MD)
//  O:      [5*SZ_MD, 6*SZ_MD)
//  f:      [6*SZ_MD, 10*SZ_MD)      (6528*512)
//  Katt:   [10*SZ_MD, 12*SZ_MD)     (6528*256)
//  Vatt:   [12*SZ_MD, 14*SZ_MD)
//  Kfin:   [14*SZ_MD, 15*SZ_MD)
//  part:   [15*SZ_MD, +16384)
//  mean:   +128, rstd: +128, pe: +6400
//  Kc:     +1638400, Vc: +1638400
#define OFF_T    (SZ_MD)
#define OFF_Q    (2*SZ_MD)
#define OFF_K    (3*SZ_MD)
#define OFF_V    (4*SZ_MD)
#define OFF_O    (5*SZ_MD)
#define OFF_F    (6*SZ_MD)
#define OFF_KATT (10*SZ_MD)
#define OFF_VATT (12*SZ_MD)
#define OFF_KFIN (14*SZ_MD)
#define OFF_PART (15*SZ_MD)
#define OFF_MEAN (OFF_PART + 16384)
#define OFF_RSTD (OFF_MEAN + 128)
#define OFF_PE   (OFF_RSTD + 128)
#define OFF_KC   (OFF_PE + NNOD*DIM)
#define SZ_KC    (NLD*BB*NH*NNOD*DHE)
#define OFF_VC   (OFF_KC + SZ_KC)
#define SCRATCH_TOTAL (OFF_VC + SZ_KC)

__device__ float g_scratch[SCRATCH_TOTAL];

// ---------------- embedding ----------------
__global__ void embed_kernel(const float* __restrict__ x,
                             const float* __restrict__ w_in,
                             const float* __restrict__ b_in,
                             const float* __restrict__ start_ph,
                             float* __restrict__ h)
{
    int i = blockIdx.x * blockDim.x + threadIdx.x;
    if (i >= MTOT * DIM) return;
    int d = i & 127;
    int row = i >> 7;
    int s = row % SEQ;
    int b = row / SEQ;
    float v;
    if (s < NNOD) {
        const float* xp = x + (b * NNOD + s) * 2;
        v = xp[0] * w_in[d] + xp[1] * w_in[DIM + d] + b_in[d];
    } else {
        v = start_ph[d];
    }
    h[i] = v;
}

// ---------------- positional encoding (match numpy float64 table) ----------------
__global__ void pe_kernel(float* __restrict__ pe)
{
    int i = blockIdx.x * blockDim.x + threadIdx.x;
    if (i >= NNOD * DIM) return;
    int t = i >> 7, d = i & 127;
    double e = (double)(2 * (d / 2)) / 128.0;
    double ang = (double)t * pow(10000.0, -e);
    pe[i] = (float)(((d & 1) == 0) ? sin(ang) : cos(ang));
}

// ---------------- generic SGEMM: C = A[M,K] @ W[K,N] (+bias)(relu)(+res) ----------------
template<bool BIAS, bool RELU, bool RES>
__global__ void __launch_bounds__(256) sgemm(const float* __restrict__ A,
                                             const float* __restrict__ W,
                                             const float* __restrict__ bias,
                                             const float* __restrict__ R,
                                             float* __restrict__ C,
                                             int M, int N, int K)
{
    __shared__ float As[16][68];
    __shared__ float Bs[16][68];
    int bm = blockIdx.y * 64, bn = blockIdx.x * 64;
    int tid = threadIdx.x;
    int tr = tid >> 4, tc = tid & 15;
    float acc[4][4] = {};
    for (int k0 = 0; k0 < K; k0 += 16) {
        int m = tid >> 2, kk = (tid & 3) * 4;
        float4 av = *(const float4*)&A[(bm + m) * K + k0 + kk];
        As[kk + 0][m] = av.x; As[kk + 1][m] = av.y;
        As[kk + 2][m] = av.z; As[kk + 3][m] = av.w;
        int kr = tid >> 4, cc = (tid & 15) * 4;
        float4 bv = *(const float4*)&W[(k0 + kr) * N + bn + cc];
        Bs[kr][cc + 0] = bv.x; Bs[kr][cc + 1] = bv.y;
        Bs[kr][cc + 2] = bv.z; Bs[kr][cc + 3] = bv.w;
        __syncthreads();
#pragma unroll
        for (int k2 = 0; k2 < 16; k2++) {
            float ra[4], rb[4];
#pragma unroll
            for (int i = 0; i < 4; i++) { ra[i] = As[k2][tr * 4 + i]; rb[i] = Bs[k2][tc * 4 + i]; }
#pragma unroll
            for (int i = 0; i < 4; i++)
#pragma unroll
                for (int j = 0; j < 4; j++) acc[i][j] += ra[i] * rb[j];
        }
        __syncthreads();
    }
#pragma unroll
    for (int i = 0; i < 4; i++) {
        int m = bm + tr * 4 + i;
#pragma unroll
        for (int j = 0; j < 4; j++) {
            int n = bn + tc * 4 + j;
            float v = acc[i][j];
            if (BIAS) v += bias[n];
            if (RELU) v = fmaxf(v, 0.f);
            if (RES)  v += R[m * N + n];
            C[m * N + n] = v;
        }
    }
}

// ---------------- encoder attention: one block per (b, head) ----------------
__global__ void __launch_bounds__(128) enc_attn(const float* __restrict__ Q,
                                                const float* __restrict__ K,
                                                const float* __restrict__ V,
                                                float* __restrict__ O)
{
    __shared__ float Qs[SEQ][DHE], Ks[SEQ][DHE], Vs[SEQ][DHE];
    __shared__ float P[SEQ][SEQ + 1];
    int bh = blockIdx.x;
    int b = bh / NH, hh = bh % NH;
    int tid = threadIdx.x;
    for (int i = tid; i < SEQ * DHE; i += 128) {
        int s = i / DHE, j = i % DHE;
        int g = (b * SEQ + s) * DIM + hh * DHE + j;
        Qs[s][j] = Q[g]; Ks[s][j] = K[g]; Vs[s][j] = V[g];
    }
    __syncthreads();
    for (int p = tid; p < SEQ * SEQ; p += 128) {
        int q = p / SEQ, k = p % SEQ;
        float s = 0.f;
#pragma unroll
        for (int j = 0; j < DHE; j++) s += Qs[q][j] * Ks[k][j];
        P[q][k] = s * 0.25f;
    }
    __syncthreads();
    if (tid < SEQ) {
        float mx = -1e30f;
        for (int k = 0; k < SEQ; k++) mx = fmaxf(mx, P[tid][k]);
        float sum = 0.f;
        for (int k = 0; k < SEQ; k++) { float e = expf(P[tid][k] - mx); P[tid][k] = e; sum += e; }
        float inv = 1.f / sum;
        for (int k = 0; k < SEQ; k++) P[tid][k] *= inv;
    }
    __syncthreads();
    for (int p = tid; p < SEQ * DHE; p += 128) {
        int q = p / DHE, j = p % DHE;
        float s = 0.f;
        for (int k = 0; k < SEQ; k++) s += P[q][k] * Vs[k][j];
        O[(b * SEQ + q) * DIM + hh * DHE + j] = s;
    }
}

// ---------------- BatchNorm (deterministic 3-stage) ----------------
__global__ void __launch_bounds__(256) bn_partial(const float* __restrict__ X,
                                                  float* __restrict__ part)
{
    int d = threadIdx.x & 127, half = threadIdx.x >> 7;
    int r0 = blockIdx.x * 102;
    float s = 0.f, ss = 0.f;
    for (int r = r0 + half; r < r0 + 102; r += 2) {
        float v = X[r * DIM + d];
        s += v; ss += v * v;
    }
    __shared__ float sh[2][2][128];
    sh[half][0][d] = s; sh[half][1][d] = ss;
    __syncthreads();
    if (!half) {
        part[blockIdx.x * 256 + d]       = s + sh[1][0][d];
        part[blockIdx.x * 256 + 128 + d] = ss + sh[1][1][d];
    }
}

__global__ void bn_reduce(const float* __restrict__ part,
                          float* __restrict__ mean, float* __restrict__ rstd)
{
    int d = threadIdx.x;
    float s = 0.f, ss = 0.f;
    for (int b = 0; b < 64; b++) { s += part[b * 256 + d]; ss += part[b * 256 + 128 + d]; }
    float m = s * (1.f / (float)MTOT);
    float v = ss * (1.f / (float)MTOT) - m * m;
    mean[d] = m;
    rstd[d] = rsqrtf(v + 1e-5f);
}

__global__ void __launch_bounds__(256) bn_apply(const float* __restrict__ X,
                                                const float* __restrict__ mean,
                                                const float* __restrict__ rstd,
                                                const float* __restrict__ gamma,
                                                const float* __restrict__ beta,
                                                float* __restrict__ Y)
{
    int i = blockIdx.x * blockDim.x + threadIdx.x;
    if (i >= MTOT * DIM) return;
    int d = i & 127;
    Y[i] = gamma[d] * (X[i] - mean[d]) * rstd[d] + beta[d];
}

// ---------------- decoder helpers ----------------
__device__ __forceinline__ float blksum(float v, float* red)
{
#pragma unroll
    for (int o = 16; o; o >>= 1) v += __shfl_down_sync(0xffffffffu, v, o);
    if ((threadIdx.x & 31) == 0) red[threadIdx.x >> 5] = v;
    __syncthreads();
    float r = (red[0] + red[1]) + (red[2] + red[3]);
    __syncthreads();
    return r;
}

__device__ __forceinline__ void layernorm(float* u, float* ht, const float* gb,
                                          int d, float* red)
{
    float mean = blksum(u[d], red) * (1.f / 128.f);
    float diff = u[d] - mean;
    float var = blksum(diff * diff, red) * (1.f / 128.f);
    float rstd = rsqrtf(var + 1e-5f);
    ht[d] = gb[d] * diff * rstd + gb[DIM + d];
    __syncthreads();
}

// ---------------- persistent decoder: one block per batch element ----------------
__global__ void __launch_bounds__(128) decoder_kernel(
    const float* __restrict__ h_enc, const float* __restrict__ pe,
    const float* __restrict__ Katt, const float* __restrict__ Vatt,
    const float* __restrict__ Kfin,
    float* __restrict__ Kc, float* __restrict__ Vc,
    const float* __restrict__ dsw, const float* __restrict__ dsb,
    const float* __restrict__ dcw, const float* __restrict__ dcb,
    const float* __restrict__ dw1, const float* __restrict__ db1,
    const float* __restrict__ dw2, const float* __restrict__ db2,
    const float* __restrict__ dln, const float* __restrict__ wqf,
    float* __restrict__ out)
{
    int b = blockIdx.x, d = threadIdx.x;
    int hh = d >> 4, dh = d & 15;

    __shared__ float ht[DIM], sq[DIM], so[DIM], su[DIM];
    __shared__ float sf[FFD];
    __shared__ float sc[NH][SEQ + 1];
    __shared__ float red[4];
    __shared__ float slg[SEQ];
    __shared__ int   smask[SEQ];
    __shared__ int   scur;
    __shared__ float sslp;

    for (int n = d; n < SEQ; n += 128) smask[n] = (n == NNOD) ? 1 : 0;
    if (d == 0) { scur = NNOD; sslp = 0.f; }
    __syncthreads();

    for (int t = 0; t < NNOD; t++) {
        ht[d] = h_enc[(b * SEQ + scur) * DIM + d] + pe[t * DIM + d];
        __syncthreads();

        for (int l = 0; l < NLD; l++) {
            // ---- self attention QKV ----
            const float* W = dsw + l * 4 * DIM * DIM;
            const float* bb = dsb + l * 4 * DIM;
            {
                float a0 = bb[d], a1 = bb[DIM + d], a2 = bb[2 * DIM + d];
                for (int k = 0; k < DIM; k++) {
                    float hk = ht[k];
                    a0 += hk * W[k * DIM + d];
                    a1 += hk * W[DIM * DIM + k * DIM + d];
                    a2 += hk * W[2 * DIM * DIM + k * DIM + d];
                }
                sq[d] = a0;
                int cb = ((l * BB + b) * NH + hh) * NNOD * DHE;
                Kc[cb + t * DHE + dh] = a1;
                Vc[cb + t * DHE + dh] = a2;
            }
            __syncthreads();

            int nt = t + 1;
            for (int p = d; p < NH * nt; p += 128) {
                int ph = p / nt, ps = p % nt;
                const float* kp = &Kc[((l * BB + b) * NH + ph) * NNOD * DHE + ps * DHE];
                const float* qp = &sq[ph * DHE];
                float s = 0.f;
#pragma unroll
                for (int j = 0; j < DHE; j++) s += qp[j] * kp[j];
                sc[ph][ps] = s * 0.25f;
            }
            __syncthreads();
            if (d < NH) {
                float mx = -1e30f;
                for (int s = 0; s < nt; s++) mx = fmaxf(mx, sc[d][s]);
                float sm = 0.f;
                for (int s = 0; s < nt; s++) { float e = expf(sc[d][s] - mx); sc[d][s] = e; sm += e; }
                float inv = 1.f / sm;
                for (int s = 0; s < nt; s++) sc[d][s] *= inv;
            }
            __syncthreads();
            {
                float oo = 0.f;
                const float* vp = &Vc[((l * BB + b) * NH + hh) * NNOD * DHE + dh];
                for (int s = 0; s < nt; s++) oo += sc[hh][s] * vp[s * DHE];
                so[d] = oo;
            }
            __syncthreads();
            {
                const float* Wo = W + 3 * DIM * DIM;
                float a = bb[3 * DIM + d];
                for (int k = 0; k < DIM; k++) a += so[k] * Wo[k * DIM + d];
                su[d] = ht[d] + a;
            }
            __syncthreads();
            layernorm(su, ht, dln + ((l * 3 + 0) * 2) * DIM, d, red);

            // ---- cross attention ----
            const float* Wc = dcw + l * 2 * DIM * DIM;
            const float* bc = dcb + l * 2 * DIM;
            {
                float a = bc[d];
                for (int k = 0; k < DIM; k++) a += ht[k] * Wc[k * DIM + d];
                sq[d] = a;
            }
            __syncthreads();
            for (int p = d; p < NH * SEQ; p += 128) {
                int ph = p / SEQ, pn = p % SEQ;
                const float* kp = &Katt[(b * SEQ + pn) * (NLD * DIM) + l * DIM + ph * DHE];
                const float* qp = &sq[ph * DHE];
                float s = 0.f;
#pragma unroll
                for (int j = 0; j < DHE; j++) s += qp[j] * kp[j];
                sc[ph][pn] = s * 0.25f;
            }
            __syncthreads();
            if (d < NH) {
                float mx = -1e30f;
                for (int n = 0; n < SEQ; n++) mx = fmaxf(mx, sc[d][n]);
                float sm = 0.f;
                for (int n = 0; n < SEQ; n++) { float e = expf(sc[d][n] - mx); sc[d][n] = e; sm += e; }
                float inv = 1.f / sm;
                for (int n = 0; n < SEQ; n++) sc[d][n] *= inv;
            }
            __syncthreads();
            {
                float oo = 0.f;
                const float* vp = &Vatt[b * SEQ * (NLD * DIM) + l * DIM + d];
                for (int n = 0; n < SEQ; n++) oo += sc[hh][n] * vp[n * NLD * DIM];
                so[d] = oo;
            }
            __syncthreads();
            {
                const float* W2c = Wc + DIM * DIM;
                float a = bc[DIM + d];
                for (int k = 0; k < DIM; k++) a += so[k] * W2c[k * DIM + d];
                su[d] = ht[d] + a;
            }
            __syncthreads();
            layernorm(su, ht, dln + ((l * 3 + 1) * 2) * DIM, d, red);

            // ---- FFN ----
            {
                const float* W1 = dw1 + l * DIM * FFD;
                const float* b1 = db1 + l * FFD;
                float a0 = b1[d], a1 = b1[d + 128], a2 = b1[d + 256], a3 = b1[d + 384];
                for (int k = 0; k < DIM; k++) {
                    float hk = ht[k];
                    const float* wr = &W1[k * FFD + d];
                    a0 += hk * wr[0];
                    a1 += hk * wr[128];
                    a2 += hk * wr[256];
                    a3 += hk * wr[384];
                }
                sf[d]       = fmaxf(a0, 0.f);
                sf[d + 128] = fmaxf(a1, 0.f);
                sf[d + 256] = fmaxf(a2, 0.f);
                sf[d + 384] = fmaxf(a3, 0.f);
            }
            __syncthreads();
            {
                const float* W2 = dw2 + l * FFD * DIM;
                float a = db2[l * DIM + d];
                for (int k = 0; k < FFD; k++) a += sf[k] * W2[k * DIM + d];
                su[d] = ht[d] + a;
            }
            __syncthreads();
            layernorm(su, ht, dln + ((l * 3 + 2) * 2) * DIM, d, red);
        }

        // ---- final pointer logits ----
        {
            float a = 0.f;
            for (int k = 0; k < DIM; k++) a += ht[k] * wqf[k * DIM + d];
            sq[d] = a;
        }
        __syncthreads();
        for (int n = d; n < SEQ; n += 128) {
            const float* kp = &Kfin[(b * SEQ + n) * DIM];
            float s = 0.f;
            for (int k = 0; k < DIM; k++) s += sq[k] * kp[k];
            float lg = 10.f * tanhf(s * 0.08838834764831845f);   // 1/sqrt(128)
            slg[n] = smask[n] ? -1e9f : lg;
        }
        __syncthreads();
        if (d == 0) {
            float mx = -1e30f;
            int am = 0;
            for (int n = 0; n < SEQ; n++) if (slg[n] > mx) { mx = slg[n]; am = n; }
            float sm = 0.f;
            for (int n = 0; n < SEQ; n++) sm += expf(slg[n] - mx);
            sslp += -logf(sm);           // logp[am] = logits[am] - mx - log(sum) = -log(sum)
            smask[am] = 1;
            scur = am;
            out[b * NNOD + t] = (float)am;
        }
        __syncthreads();
    }
    if (d == 0) out[BB * NNOD + b] = sslp;
}

// ---------------- host launcher ----------------
extern "C" void kernel_launch(void* const* d_in, const int* in_sizes, int n_in,
                              void* d_out, int out_size)
{
    const float* x          = (const float*)d_in[0];
    const float* w_input    = (const float*)d_in[1];
    const float* b_input    = (const float*)d_in[2];
    const float* start_ph   = (const float*)d_in[3];
    const float* enc_attn_w = (const float*)d_in[4];
    const float* enc_attn_b = (const float*)d_in[5];
    const float* enc_ffn_w1 = (const float*)d_in[6];
    const float* enc_ffn_b1 = (const float*)d_in[7];
    const float* enc_ffn_w2 = (const float*)d_in[8];
    const float* enc_ffn_b2 = (const float*)d_in[9];
    const float* enc_bn     = (const float*)d_in[10];
    const float* dec_self_w = (const float*)d_in[11];
    const float* dec_self_b = (const float*)d_in[12];
    const float* dec_cross_w= (const float*)d_in[13];
    const float* dec_cross_b= (const float*)d_in[14];
    const float* dec_ffn_w1 = (const float*)d_in[15];
    const float* dec_ffn_b1 = (const float*)d_in[16];
    const float* dec_ffn_w2 = (const float*)d_in[17];
    const float* dec_ffn_b2 = (const float*)d_in[18];
    const float* dec_ln     = (const float*)d_in[19];
    const float* wk_dec     = (const float*)d_in[20];
    const float* bk_dec     = (const float*)d_in[21];
    const float* wv_dec     = (const float*)d_in[22];
    const float* bv_dec     = (const float*)d_in[23];
    const float* wq_final   = (const float*)d_in[24];
    const float* wk_final   = (const float*)d_in[25];
    float* out = (float*)d_out;

    float* base = nullptr;
    cudaGetSymbolAddress((void**)&base, g_scratch);
    float* ph    = base;
    float* pt    = base + OFF_T;
    float* pQ    = base + OFF_Q;
    float* pK    = base + OFF_K;
    float* pV    = base + OFF_V;
    float* pO    = base + OFF_O;
    float* pf    = base + OFF_F;
    float* pKatt = base + OFF_KATT;
    float* pVatt = base + OFF_VATT;
    float* pKfin = base + OFF_KFIN;
    float* ppart = base + OFF_PART;
    float* pmean = base + OFF_MEAN;
    float* prstd = base + OFF_RSTD;
    float* ppe   = base + OFF_PE;
    float* pKc   = base + OFF_KC;
    float* pVc   = base + OFF_VC;

    embed_kernel<<<(MTOT * DIM + 255) / 256, 256>>>(x, w_input, b_input, start_ph, ph);
    pe_kernel<<<(NNOD * DIM + 255) / 256, 256>>>(ppe);

    dim3 gDD(DIM / 64, MTOT / 64);     // N=128
    dim3 gDF(FFD / 64, MTOT / 64);     // N=512
    dim3 gD2(256 / 64, MTOT / 64);     // N=256

    for (int l = 0; l < NLE; l++) {
        const float* aw = enc_attn_w + (size_t)l * 4 * DIM * DIM;
        const float* ab = enc_attn_b + (size_t)l * 4 * DIM;
        sgemm<true, false, false><<<gDD, 256>>>(ph, aw,                 ab,           nullptr, pQ, MTOT, DIM, DIM);
        sgemm<true, false, false><<<gDD, 256>>>(ph, aw + DIM * DIM,     ab + DIM,     nullptr, pK, MTOT, DIM, DIM);
        sgemm<true, false, false><<<gDD, 256>>>(ph, aw + 2 * DIM * DIM, ab + 2 * DIM, nullptr, pV, MTOT, DIM, DIM);
        enc_attn<<<BB * NH, 128>>>(pQ, pK, pV, pO);
        sgemm<true, false, true><<<gDD, 256>>>(pO, aw + 3 * DIM * DIM, ab + 3 * DIM, ph, pt, MTOT, DIM, DIM);
        bn_partial<<<64, 256>>>(pt, ppart);
        bn_reduce<<<1, 128>>>(ppart, pmean, prstd);
        bn_apply<<<(MTOT * DIM + 255) / 256, 256>>>(pt, pmean, prstd,
                 enc_bn + ((l * 2 + 0) * 2 + 0) * DIM, enc_bn + ((l * 2 + 0) * 2 + 1) * DIM, ph);
        sgemm<true, true, false><<<gDF, 256>>>(ph, enc_ffn_w1 + (size_t)l * DIM * FFD,
                 enc_ffn_b1 + (size_t)l * FFD, nullptr, pf, MTOT, FFD, DIM);
        sgemm<true, false, true><<<gDD, 256>>>(pf, enc_ffn_w2 + (size_t)l * FFD * DIM,
                 enc_ffn_b2 + (size_t)l * DIM, ph, pt, MTOT, DIM, FFD);
        bn_partial<<<64, 256>>>(pt, ppart);
        bn_reduce<<<1, 128>>>(ppart, pmean, prstd);
        bn_apply<<<(MTOT * DIM + 255) / 256, 256>>>(pt, pmean, prstd,
                 enc_bn + ((l * 2 + 1) * 2 + 0) * DIM, enc_bn + ((l * 2 + 1) * 2 + 1) * DIM, ph);
    }

    // decoder cross-attn K/V and final pointer keys
    sgemm<true,  false, false><<<gD2, 256>>>(ph, wk_dec,   bk_dec,  nullptr, pKatt, MTOT, NLD * DIM, DIM);
    sgemm<true,  false, false><<<gD2, 256>>>(ph, wv_dec,   bv_dec,  nullptr, pVatt, MTOT, NLD * DIM, DIM);
    sgemm<false, false, false><<<gDD, 256>>>(ph, wk_final, nullptr, nullptr, pKfin, MTOT, DIM, DIM);

    decoder_kernel<<<BB, 128>>>(ph, ppe, pKatt, pVatt, pKfin, pKc, pVc,
                                dec_self_w, dec_self_b, dec_cross_w, dec_cross_b,
                                dec_ffn_w1, dec_ffn_b1, dec_ffn_w2, dec_ffn_b2,
                                dec_ln, wq_final, out);
}